// round 1
// baseline (speedup 1.0000x reference)
#include <cuda_runtime.h>
#include <math.h>

#define Dm 512
#define Cm 100
#define Nm 2048
#define DDm (Dm*Dm)

#define ALPHA 0.5f
#define SHRINK 1e-4f

// ---------------- scratch (device globals; no runtime allocation) ----------------
__device__ float g_M[(size_t)Cm*DDm];    // M_k, overwritten in-place by L_k (lower)
__device__ float g_UT[(size_t)Cm*DDm];   // UT[d][e] = U[e][d],  U = L^{-1} (lower)
__device__ float g_XT[(size_t)Dm*Nm];    // X transposed [D][N]
__device__ float g_w[Cm*Dm];             // w_k = U_k mu_k
__device__ float g_cc[Cm];               // log(prior_k) - 0.25*log(fro2_k)  (or -inf)
__device__ float g_fro2[Cm];             // ||RegSigma_k||_F^2

// ---------------- K0: transpose X -> XT ----------------
__global__ void transpose_x(const float* __restrict__ X) {
    __shared__ float t[32][33];
    int bx = blockIdx.x * 32;   // n
    int by = blockIdx.y * 32;   // d
    int tx = threadIdx.x, ty0 = threadIdx.y;
    #pragma unroll
    for (int ty = ty0; ty < 32; ty += 8)
        t[ty][tx] = X[(size_t)(bx+ty)*Dm + by + tx];
    __syncthreads();
    #pragma unroll
    for (int ty = ty0; ty < 32; ty += 8)
        g_XT[(size_t)(by+ty)*Nm + bx + tx] = t[tx][ty];
}

// ---------------- K1: build M_k and Frobenius norm ----------------
__global__ void build_M(const float* __restrict__ SigmaK, const float* __restrict__ Sigma) {
    int c = blockIdx.x;
    const float4* Sk = (const float4*)(SigmaK + (size_t)c*DDm);
    const float4* Sg = (const float4*)Sigma;
    float4* M = (float4*)(g_M + (size_t)c*DDm);
    int tid = threadIdx.x;
    float fro = 0.f;
    for (int i = tid; i < DDm/4; i += 256) {
        float4 a = Sk[i];
        float4 b = Sg[i];
        int e0 = i*4;
        float r0 = ALPHA*a.x + (1.f-ALPHA)*b.x;
        float r1 = ALPHA*a.y + (1.f-ALPHA)*b.y;
        float r2 = ALPHA*a.z + (1.f-ALPHA)*b.z;
        float r3 = ALPHA*a.w + (1.f-ALPHA)*b.w;
        fro += r0*r0 + r1*r1 + r2*r2 + r3*r3;
        float4 m;
        m.x = (1.f-SHRINK)*r0 + ((((e0+0)>>9) == ((e0+0)&511)) ? SHRINK : 0.f);
        m.y = (1.f-SHRINK)*r1 + ((((e0+1)>>9) == ((e0+1)&511)) ? SHRINK : 0.f);
        m.z = (1.f-SHRINK)*r2 + ((((e0+2)>>9) == ((e0+2)&511)) ? SHRINK : 0.f);
        m.w = (1.f-SHRINK)*r3 + ((((e0+3)>>9) == ((e0+3)&511)) ? SHRINK : 0.f);
        M[i] = m;
    }
    __shared__ float red[256];
    red[tid] = fro;
    __syncthreads();
    for (int s = 128; s > 0; s >>= 1) {
        if (tid < s) red[tid] += red[tid+s];
        __syncthreads();
    }
    if (tid == 0) g_fro2[c] = red[0];
}

// ---------------- K2: per-class constants ----------------
__global__ void class_consts(const float* __restrict__ cK) {
    __shared__ float ssum[128];
    int tid = threadIdx.x;
    float s = 0.f;
    for (int i = tid; i < Cm; i += 128) s += cK[i];
    ssum[tid] = s;
    __syncthreads();
    for (int st = 64; st > 0; st >>= 1) {
        if (tid < st) ssum[tid] += ssum[tid+st];
        __syncthreads();
    }
    float tot = ssum[0];
    if (tid < Cm) {
        float ck = cK[tid];
        float cc;
        if (ck <= 0.f) cc = -INFINITY;
        else cc = logf(ck / tot) - 0.25f*logf(g_fro2[tid]);
        g_cc[tid] = cc;
    }
}

// ---------------- K3: left-looking blocked Cholesky (in place, lower) ----------------
#define CHOL_SMEM ((512*65 + 2*64*65)*4)
__global__ void __launch_bounds__(256) cholesky_k() {
    int c = blockIdx.x;
    float* A = g_M + (size_t)c*DDm;
    extern __shared__ float sm[];
    float* P  = sm;              // [512][65] panel
    float* Lt = sm + 512*65;     // [64][65] history block at panel-top rows
    float* Lr = Lt + 64*65;      // [64][65] history block at target rows
    int tid = threadIdx.x;
    int tx = tid & 15, ty = tid >> 4;
    for (int jb = 0; jb < 8; jb++) {
        int col0 = jb*64;
        int nr = Dm - col0;
        for (int i = tid; i < nr*64; i += 256) {
            int r = i >> 6, j = i & 63;
            P[r*65+j] = A[(size_t)(col0+r)*Dm + col0 + j];
        }
        __syncthreads();
        for (int kb = 0; kb < jb; kb++) {
            for (int i = tid; i < 64*64; i += 256) {
                int r = i >> 6, k = i & 63;
                Lt[r*65+k] = A[(size_t)(col0+r)*Dm + kb*64 + k];
            }
            __syncthreads();
            for (int r0 = 0; r0 < nr; r0 += 64) {
                const float* Lp = Lt;
                if (r0 != 0) {
                    for (int i = tid; i < 64*64; i += 256) {
                        int r = i >> 6, k = i & 63;
                        Lr[r*65+k] = A[(size_t)(col0+r0+r)*Dm + kb*64 + k];
                    }
                    Lp = Lr;
                }
                __syncthreads();
                float acc[4][4];
                #pragma unroll
                for (int a = 0; a < 4; a++)
                    #pragma unroll
                    for (int b = 0; b < 4; b++) acc[a][b] = 0.f;
                #pragma unroll 8
                for (int k = 0; k < 64; k++) {
                    float av[4], bv[4];
                    #pragma unroll
                    for (int a = 0; a < 4; a++) av[a] = Lp[(ty*4+a)*65 + k];
                    #pragma unroll
                    for (int b = 0; b < 4; b++) bv[b] = Lt[(tx*4+b)*65 + k];
                    #pragma unroll
                    for (int a = 0; a < 4; a++)
                        #pragma unroll
                        for (int b = 0; b < 4; b++) acc[a][b] += av[a]*bv[b];
                }
                #pragma unroll
                for (int a = 0; a < 4; a++)
                    #pragma unroll
                    for (int b = 0; b < 4; b++)
                        P[(r0+ty*4+a)*65 + tx*4+b] -= acc[a][b];
                __syncthreads();
            }
        }
        // factor 64-wide panel (right-looking within panel)
        for (int j = 0; j < 64; j++) {
            if (tid == 0) P[j*65+j] = sqrtf(P[j*65+j]);
            __syncthreads();
            float dinv = 1.0f / P[j*65+j];
            for (int r = j+1+tid; r < nr; r += 256) P[r*65+j] *= dinv;
            __syncthreads();
            int ncols = 63 - j;
            int nrows = nr - (j+1);
            for (int i = tid; i < nrows*ncols; i += 256) {
                int rr = i / ncols;
                int r = j+1 + rr;
                int k = j+1 + (i - rr*ncols);
                P[r*65+k] -= P[r*65+j]*P[k*65+j];
            }
            __syncthreads();
        }
        for (int i = tid; i < nr*64; i += 256) {
            int r = i >> 6, j = i & 63;
            A[(size_t)(col0+r)*Dm + col0 + j] = P[r*65+j];
        }
        __syncthreads();
    }
}

// ---------------- K4: invert 64x64 diagonal blocks of L, write into UT ----------------
__global__ void diag_inv() {
    int blk = blockIdx.x;
    int c = blk >> 3, ib = blk & 7;
    const float* A = g_M + (size_t)c*DDm + (size_t)(ib*64)*Dm + ib*64;
    float* UT = g_UT + (size_t)c*DDm;
    __shared__ float Ls[64][65];
    __shared__ float Xs[64][64];
    int t = threadIdx.x;  // column of inverse
    for (int r = 0; r < 64; r++) Ls[r][t] = A[(size_t)r*Dm + t];
    __syncthreads();
    for (int r = 0; r < 64; r++) {
        float v;
        if (r < t) v = 0.f;
        else if (r == t) v = 1.0f / Ls[r][r];
        else {
            float s = 0.f;
            for (int k = t; k < r; k++) s += Ls[r][k]*Xs[k][t];
            v = -s / Ls[r][r];
        }
        Xs[r][t] = v;
    }
    __syncthreads();
    // U_ii[r][t] = Xs[r][t]  ->  UT[ib*64+t][ib*64+r]
    for (int r = 0; r < 64; r++)
        UT[(size_t)(ib*64 + t)*Dm + ib*64 + r] = Xs[r][t];
}

// ---------------- K5: off-diagonal blocks of U = L^{-1} (stored transposed) ----------------
#define OFF_SMEM (4*64*65*4)
__global__ void __launch_bounds__(256) trinv_offdiag() {
    int c = blockIdx.x;
    const float* L = g_M + (size_t)c*DDm;
    float* UT = g_UT + (size_t)c*DDm;
    extern __shared__ float sm[];
    float* As  = sm;             // L_ik [r][kk]
    float* Bs  = As + 64*65;     // U_kj [kk][cj]
    float* Ts  = Bs + 64*65;     // T    [r][cj]
    float* Ais = Ts + 64*65;     // U_ii [r][kk]
    int tid = threadIdx.x, tx = tid & 15, ty = tid >> 4;
    for (int j = 0; j < 7; j++) {
        for (int i = j+1; i < 8; i++) {
            float acc[4][4];
            #pragma unroll
            for (int a = 0; a < 4; a++)
                #pragma unroll
                for (int b = 0; b < 4; b++) acc[a][b] = 0.f;
            for (int kblk = j; kblk < i; kblk++) {
                __syncthreads();
                for (int idx = tid; idx < 64*64; idx += 256) {
                    int r = idx >> 6, kk = idx & 63;
                    As[r*65+kk] = L[(size_t)(i*64+r)*Dm + kblk*64 + kk];
                }
                for (int idx = tid; idx < 64*64; idx += 256) {
                    int cj = idx >> 6, kk = idx & 63;
                    Bs[kk*65+cj] = UT[(size_t)(j*64+cj)*Dm + kblk*64 + kk];
                }
                __syncthreads();
                #pragma unroll 8
                for (int kk = 0; kk < 64; kk++) {
                    float av[4], bv[4];
                    #pragma unroll
                    for (int a = 0; a < 4; a++) av[a] = As[(ty*4+a)*65 + kk];
                    #pragma unroll
                    for (int b = 0; b < 4; b++) bv[b] = Bs[kk*65 + tx*4+b];
                    #pragma unroll
                    for (int a = 0; a < 4; a++)
                        #pragma unroll
                        for (int b = 0; b < 4; b++) acc[a][b] += av[a]*bv[b];
                }
            }
            __syncthreads();
            #pragma unroll
            for (int a = 0; a < 4; a++)
                #pragma unroll
                for (int b = 0; b < 4; b++)
                    Ts[(ty*4+a)*65 + tx*4+b] = acc[a][b];
            for (int idx = tid; idx < 64*64; idx += 256) {
                int kk = idx >> 6, r = idx & 63;
                // U_ii[r][kk] = UT[i*64+kk][i*64+r]
                Ais[r*65+kk] = UT[(size_t)(i*64+kk)*Dm + i*64 + r];
            }
            __syncthreads();
            float acc2[4][4];
            #pragma unroll
            for (int a = 0; a < 4; a++)
                #pragma unroll
                for (int b = 0; b < 4; b++) acc2[a][b] = 0.f;
            #pragma unroll 8
            for (int kk = 0; kk < 64; kk++) {
                float av[4], bv[4];
                #pragma unroll
                for (int a = 0; a < 4; a++) av[a] = Ais[(ty*4+a)*65 + kk];
                #pragma unroll
                for (int b = 0; b < 4; b++) bv[b] = Ts[kk*65 + tx*4+b];
                #pragma unroll
                for (int a = 0; a < 4; a++)
                    #pragma unroll
                    for (int b = 0; b < 4; b++) acc2[a][b] += av[a]*bv[b];
            }
            // U_ij[r][cj] = -acc2 -> UT[j*64+cj][i*64+r]
            #pragma unroll
            for (int b = 0; b < 4; b++)
                #pragma unroll
                for (int a = 0; a < 4; a++)
                    UT[(size_t)(j*64 + tx*4+b)*Dm + i*64 + ty*4+a] = -acc2[a][b];
            __syncthreads();
        }
    }
}

// ---------------- K6: w_k = U_k mu_k ----------------
__global__ void compute_w(const float* __restrict__ muK) {
    int c = blockIdx.x;
    __shared__ float mus[Dm];
    int tid = threadIdx.x;
    for (int i = tid; i < Dm; i += 256) mus[i] = muK[(size_t)c*Dm + i];
    __syncthreads();
    const float* UT = g_UT + (size_t)c*DDm;
    for (int e = tid; e < Dm; e += 256) {
        float s = 0.f;
        for (int d = 0; d <= e; d++) s += UT[(size_t)d*Dm + e] * mus[d];
        g_w[(size_t)c*Dm + e] = s;
    }
}

// ---------------- K7: fused triangular GEMM + squared-distance + scores ----------------
#define MAIN_SMEM ((64*128 + 64*68)*4)
__global__ void __launch_bounds__(256) rda_main(float* __restrict__ out) {
    int c  = blockIdx.y;
    int m0 = blockIdx.x * 128;
    extern __shared__ float sm[];
    float* Xs = sm;              // [64 k][128 r]
    float* Us = sm + 64*128;     // [64 k][68 e]
    const float* UT = g_UT + (size_t)c*DDm;
    int tid = threadIdx.x, tx = tid & 15, ty = tid >> 4;
    float q[8];
    #pragma unroll
    for (int a = 0; a < 8; a++) q[a] = 0.f;

    for (int e0 = 0; e0 < Dm; e0 += 64) {
        float g[8][4];
        #pragma unroll
        for (int a = 0; a < 8; a++)
            #pragma unroll
            for (int b = 0; b < 4; b++) g[a][b] = 0.f;
        for (int d0 = 0; d0 <= e0; d0 += 64) {
            __syncthreads();
            // Xs[k][r] = XT[d0+k][m0+r]
            for (int idx = tid; idx < 64*32; idx += 256) {
                int k  = idx >> 5;
                int r4 = (idx & 31) * 4;
                float4 v = *(const float4*)&g_XT[(size_t)(d0+k)*Nm + m0 + r4];
                *(float4*)&Xs[k*128 + r4] = v;
            }
            // Us[k][e] = UT[d0+k][e0+e]   (zero above diagonal by construction)
            for (int idx = tid; idx < 64*16; idx += 256) {
                int k  = idx >> 4;
                int e4 = (idx & 15) * 4;
                float4 v = *(const float4*)&UT[(size_t)(d0+k)*Dm + e0 + e4];
                *(float4*)&Us[k*68 + e4] = v;
            }
            __syncthreads();
            #pragma unroll 16
            for (int k = 0; k < 64; k++) {
                float4 x0 = *(const float4*)&Xs[k*128 + ty*8];
                float4 x1 = *(const float4*)&Xs[k*128 + ty*8 + 4];
                float4 u  = *(const float4*)&Us[k*68 + tx*4];
                float xa[8] = {x0.x,x0.y,x0.z,x0.w,x1.x,x1.y,x1.z,x1.w};
                float ub[4] = {u.x,u.y,u.z,u.w};
                #pragma unroll
                for (int a = 0; a < 8; a++)
                    #pragma unroll
                    for (int b = 0; b < 4; b++)
                        g[a][b] += xa[a]*ub[b];
            }
        }
        float4 wv = *(const float4*)&g_w[(size_t)c*Dm + e0 + tx*4];
        float wb[4] = {wv.x, wv.y, wv.z, wv.w};
        #pragma unroll
        for (int a = 0; a < 8; a++)
            #pragma unroll
            for (int b = 0; b < 4; b++) {
                float dgl = g[a][b] - wb[b];
                q[a] += dgl*dgl;
            }
    }
    // reduce across the 16 tx lanes (same warp, groups of 16)
    #pragma unroll
    for (int off = 8; off > 0; off >>= 1)
        #pragma unroll
        for (int a = 0; a < 8; a++)
            q[a] += __shfl_xor_sync(0xffffffffu, q[a], off, 16);
    if (tx == 0) {
        float cc = g_cc[c];
        #pragma unroll
        for (int a = 0; a < 8; a++)
            out[(size_t)(m0 + ty*8 + a)*Cm + c] = cc - 0.5f*q[a];
    }
}

// ---------------- launcher ----------------
extern "C" void kernel_launch(void* const* d_in, const int* in_sizes, int n_in,
                              void* d_out, int out_size) {
    const float *X = nullptr, *muK = nullptr, *SigmaK = nullptr, *Sigma = nullptr, *cK = nullptr;
    for (int i = 0; i < n_in; i++) {
        switch (in_sizes[i]) {
            case Nm*Dm:        X      = (const float*)d_in[i]; break;  // 1048576
            case Cm*Dm:        muK    = (const float*)d_in[i]; break;  // 51200
            case Cm*Dm*Dm:     SigmaK = (const float*)d_in[i]; break;  // 26214400
            case Dm*Dm:        Sigma  = (const float*)d_in[i]; break;  // 262144
            case Cm:           cK     = (const float*)d_in[i]; break;  // 100
            default: break;
        }
    }
    if (!X || !muK || !SigmaK || !Sigma || !cK) return;

    cudaFuncSetAttribute(cholesky_k,    cudaFuncAttributeMaxDynamicSharedMemorySize, CHOL_SMEM);
    cudaFuncSetAttribute(trinv_offdiag, cudaFuncAttributeMaxDynamicSharedMemorySize, OFF_SMEM);
    cudaFuncSetAttribute(rda_main,      cudaFuncAttributeMaxDynamicSharedMemorySize, MAIN_SMEM);

    transpose_x<<<dim3(Nm/32, Dm/32), dim3(32, 8)>>>(X);
    build_M<<<Cm, 256>>>(SigmaK, Sigma);
    class_consts<<<1, 128>>>(cK);
    cholesky_k<<<Cm, 256, CHOL_SMEM>>>();
    diag_inv<<<Cm*8, 64>>>();
    trinv_offdiag<<<Cm, 256, OFF_SMEM>>>();
    compute_w<<<Cm, 256>>>(muK);
    rda_main<<<dim3(Nm/128, Cm), 256, MAIN_SMEM>>>((float*)d_out);
}

// round 2
// speedup vs baseline: 1.3476x; 1.3476x over previous
#include <cuda_runtime.h>
#include <math.h>
#include <stdint.h>

#define Dm 512
#define Cm 100
#define Nm 2048
#define DDm (Dm*Dm)

#define ALPHA 0.5f
#define SHRINK 1e-4f

// ---------------- scratch (device globals; no runtime allocation) ----------------
__device__ float g_M[(size_t)Cm*DDm];    // M_k, overwritten in-place by L_k (lower)
__device__ float g_UT[(size_t)Cm*DDm];   // UT[d][e] = U[e][d],  U = L^{-1} (lower); upper zeroed
__device__ float g_XT[(size_t)Dm*Nm];    // X transposed [D][N]
__device__ float g_w[Cm*Dm];             // w_k = U_k mu_k
__device__ float g_cc[Cm];               // log(prior_k) - 0.25*log(fro2_k)  (or -inf)
__device__ float g_fro2[Cm];             // ||RegSigma_k||_F^2

// ---------------- K0: transpose X -> XT ----------------
__global__ void transpose_x(const float* __restrict__ X) {
    __shared__ float t[32][33];
    int bx = blockIdx.x * 32;   // n
    int by = blockIdx.y * 32;   // d
    int tx = threadIdx.x, ty0 = threadIdx.y;
    #pragma unroll
    for (int ty = ty0; ty < 32; ty += 8)
        t[ty][tx] = X[(size_t)(bx+ty)*Dm + by + tx];
    __syncthreads();
    #pragma unroll
    for (int ty = ty0; ty < 32; ty += 8)
        g_XT[(size_t)(by+ty)*Nm + bx + tx] = t[tx][ty];
}

// ---------------- K1: build M_k and Frobenius norm ----------------
__global__ void build_M(const float* __restrict__ SigmaK, const float* __restrict__ Sigma) {
    int c = blockIdx.x;
    const float4* Sk = (const float4*)(SigmaK + (size_t)c*DDm);
    const float4* Sg = (const float4*)Sigma;
    float4* M = (float4*)(g_M + (size_t)c*DDm);
    int tid = threadIdx.x;
    float fro = 0.f;
    for (int i = tid; i < DDm/4; i += 256) {
        float4 a = Sk[i];
        float4 b = Sg[i];
        int e0 = i*4;
        float r0 = ALPHA*a.x + (1.f-ALPHA)*b.x;
        float r1 = ALPHA*a.y + (1.f-ALPHA)*b.y;
        float r2 = ALPHA*a.z + (1.f-ALPHA)*b.z;
        float r3 = ALPHA*a.w + (1.f-ALPHA)*b.w;
        fro += r0*r0 + r1*r1 + r2*r2 + r3*r3;
        float4 m;
        m.x = (1.f-SHRINK)*r0 + ((((e0+0)>>9) == ((e0+0)&511)) ? SHRINK : 0.f);
        m.y = (1.f-SHRINK)*r1 + ((((e0+1)>>9) == ((e0+1)&511)) ? SHRINK : 0.f);
        m.z = (1.f-SHRINK)*r2 + ((((e0+2)>>9) == ((e0+2)&511)) ? SHRINK : 0.f);
        m.w = (1.f-SHRINK)*r3 + ((((e0+3)>>9) == ((e0+3)&511)) ? SHRINK : 0.f);
        M[i] = m;
    }
    __shared__ float red[256];
    red[tid] = fro;
    __syncthreads();
    for (int s = 128; s > 0; s >>= 1) {
        if (tid < s) red[tid] += red[tid+s];
        __syncthreads();
    }
    if (tid == 0) g_fro2[c] = red[0];
}

// ---------------- K2: per-class constants ----------------
__global__ void class_consts(const float* __restrict__ cK) {
    __shared__ float ssum[128];
    int tid = threadIdx.x;
    float s = 0.f;
    for (int i = tid; i < Cm; i += 128) s += cK[i];
    ssum[tid] = s;
    __syncthreads();
    for (int st = 64; st > 0; st >>= 1) {
        if (tid < st) ssum[tid] += ssum[tid+st];
        __syncthreads();
    }
    float tot = ssum[0];
    if (tid < Cm) {
        float ck = cK[tid];
        float cc;
        if (ck <= 0.f) cc = -INFINITY;
        else cc = logf(ck / tot) - 0.25f*logf(g_fro2[tid]);
        g_cc[tid] = cc;
    }
}

// ---------------- K3: left-looking blocked Cholesky (in place, lower) ----------------
#define CHOL_SMEM ((512*65 + 2*64*65)*4)
__global__ void __launch_bounds__(256) cholesky_k() {
    int c = blockIdx.x;
    float* A = g_M + (size_t)c*DDm;
    extern __shared__ float sm[];
    float* P  = sm;              // [512][65] panel
    float* Lt = sm + 512*65;     // [64][65] history block at panel-top rows
    float* Lr = Lt + 64*65;      // [64][65] history block at target rows
    int tid = threadIdx.x;
    int tx = tid & 15, ty = tid >> 4;
    for (int jb = 0; jb < 8; jb++) {
        int col0 = jb*64;
        int nr = Dm - col0;
        for (int i = tid; i < nr*64; i += 256) {
            int r = i >> 6, j = i & 63;
            P[r*65+j] = A[(size_t)(col0+r)*Dm + col0 + j];
        }
        __syncthreads();
        for (int kb = 0; kb < jb; kb++) {
            for (int i = tid; i < 64*64; i += 256) {
                int r = i >> 6, k = i & 63;
                Lt[r*65+k] = A[(size_t)(col0+r)*Dm + kb*64 + k];
            }
            __syncthreads();
            for (int r0 = 0; r0 < nr; r0 += 64) {
                const float* Lp = Lt;
                if (r0 != 0) {
                    for (int i = tid; i < 64*64; i += 256) {
                        int r = i >> 6, k = i & 63;
                        Lr[r*65+k] = A[(size_t)(col0+r0+r)*Dm + kb*64 + k];
                    }
                    Lp = Lr;
                }
                __syncthreads();
                float acc[4][4];
                #pragma unroll
                for (int a = 0; a < 4; a++)
                    #pragma unroll
                    for (int b = 0; b < 4; b++) acc[a][b] = 0.f;
                #pragma unroll 8
                for (int k = 0; k < 64; k++) {
                    float av[4], bv[4];
                    #pragma unroll
                    for (int a = 0; a < 4; a++) av[a] = Lp[(ty*4+a)*65 + k];
                    #pragma unroll
                    for (int b = 0; b < 4; b++) bv[b] = Lt[(tx*4+b)*65 + k];
                    #pragma unroll
                    for (int a = 0; a < 4; a++)
                        #pragma unroll
                        for (int b = 0; b < 4; b++) acc[a][b] += av[a]*bv[b];
                }
                #pragma unroll
                for (int a = 0; a < 4; a++)
                    #pragma unroll
                    for (int b = 0; b < 4; b++)
                        P[(r0+ty*4+a)*65 + tx*4+b] -= acc[a][b];
                __syncthreads();
            }
        }
        // factor 64-wide panel (no integer division in the hot loop)
        for (int j = 0; j < 64; j++) {
            if (tid == 0) P[j*65+j] = sqrtf(P[j*65+j]);
            __syncthreads();
            float dinv = 1.0f / P[j*65+j];
            for (int r = j+1+tid; r < nr; r += 256) P[r*65+j] *= dinv;
            __syncthreads();
            for (int r = j+1+tid; r < nr; r += 256) {
                float lrj = P[r*65+j];
                #pragma unroll 4
                for (int k = j+1; k < 64; k++)
                    P[r*65+k] -= lrj * P[k*65+j];
            }
            __syncthreads();
        }
        for (int i = tid; i < nr*64; i += 256) {
            int r = i >> 6, j = i & 63;
            A[(size_t)(col0+r)*Dm + col0 + j] = P[r*65+j];
        }
        __syncthreads();
    }
}

// ---------------- K4: invert 64x64 diagonal blocks of L, write into UT ----------------
__global__ void diag_inv() {
    int blk = blockIdx.x;
    int c = blk >> 3, ib = blk & 7;
    const float* A = g_M + (size_t)c*DDm + (size_t)(ib*64)*Dm + ib*64;
    float* UT = g_UT + (size_t)c*DDm;
    __shared__ float Ls[64][65];
    __shared__ float Xs[64][64];
    int t = threadIdx.x;  // column of inverse
    for (int r = 0; r < 64; r++) Ls[r][t] = A[(size_t)r*Dm + t];
    __syncthreads();
    for (int r = 0; r < 64; r++) {
        float v;
        if (r < t) v = 0.f;
        else if (r == t) v = 1.0f / Ls[r][r];
        else {
            float s = 0.f;
            for (int k = t; k < r; k++) s += Ls[r][k]*Xs[k][t];
            v = -s / Ls[r][r];
        }
        Xs[r][t] = v;
    }
    __syncthreads();
    for (int r = 0; r < 64; r++)
        UT[(size_t)(ib*64 + t)*Dm + ib*64 + r] = Xs[r][t];
}

// ---------------- K5: off-diagonal blocks of U = L^{-1}, parallel over columns j ----------------
#define OFF_SMEM (4*64*65*4)
__global__ void __launch_bounds__(256) trinv_offdiag() {
    int c = blockIdx.x;
    int j = blockIdx.y;            // 0..6
    const float* L = g_M + (size_t)c*DDm;
    float* UT = g_UT + (size_t)c*DDm;
    extern __shared__ float sm[];
    float* As  = sm;             // L_ik [r][kk]
    float* Bs  = As + 64*65;     // U_kj [kk][cj]
    float* Ts  = Bs + 64*65;     // T    [r][cj]
    float* Ais = Ts + 64*65;     // U_ii [r][kk]
    int tid = threadIdx.x, tx = tid & 15, ty = tid >> 4;
    for (int i = j+1; i < 8; i++) {
        float acc[4][4];
        #pragma unroll
        for (int a = 0; a < 4; a++)
            #pragma unroll
            for (int b = 0; b < 4; b++) acc[a][b] = 0.f;
        for (int kblk = j; kblk < i; kblk++) {
            __syncthreads();
            for (int idx = tid; idx < 64*64; idx += 256) {
                int r = idx >> 6, kk = idx & 63;
                As[r*65+kk] = L[(size_t)(i*64+r)*Dm + kblk*64 + kk];
            }
            for (int idx = tid; idx < 64*64; idx += 256) {
                int cj = idx >> 6, kk = idx & 63;
                Bs[kk*65+cj] = UT[(size_t)(j*64+cj)*Dm + kblk*64 + kk];
            }
            __syncthreads();
            #pragma unroll 8
            for (int kk = 0; kk < 64; kk++) {
                float av[4], bv[4];
                #pragma unroll
                for (int a = 0; a < 4; a++) av[a] = As[(ty*4+a)*65 + kk];
                #pragma unroll
                for (int b = 0; b < 4; b++) bv[b] = Bs[kk*65 + tx*4+b];
                #pragma unroll
                for (int a = 0; a < 4; a++)
                    #pragma unroll
                    for (int b = 0; b < 4; b++) acc[a][b] += av[a]*bv[b];
            }
        }
        __syncthreads();
        #pragma unroll
        for (int a = 0; a < 4; a++)
            #pragma unroll
            for (int b = 0; b < 4; b++)
                Ts[(ty*4+a)*65 + tx*4+b] = acc[a][b];
        for (int idx = tid; idx < 64*64; idx += 256) {
            int kk = idx >> 6, r = idx & 63;
            Ais[r*65+kk] = UT[(size_t)(i*64+kk)*Dm + i*64 + r];
        }
        __syncthreads();
        float acc2[4][4];
        #pragma unroll
        for (int a = 0; a < 4; a++)
            #pragma unroll
            for (int b = 0; b < 4; b++) acc2[a][b] = 0.f;
        #pragma unroll 8
        for (int kk = 0; kk < 64; kk++) {
            float av[4], bv[4];
            #pragma unroll
            for (int a = 0; a < 4; a++) av[a] = Ais[(ty*4+a)*65 + kk];
            #pragma unroll
            for (int b = 0; b < 4; b++) bv[b] = Ts[kk*65 + tx*4+b];
            #pragma unroll
            for (int a = 0; a < 4; a++)
                #pragma unroll
                for (int b = 0; b < 4; b++) acc2[a][b] += av[a]*bv[b];
        }
        #pragma unroll
        for (int b = 0; b < 4; b++)
            #pragma unroll
            for (int a = 0; a < 4; a++)
                UT[(size_t)(j*64 + tx*4+b)*Dm + i*64 + ty*4+a] = -acc2[a][b];
        __syncthreads();
    }
}

// ---------------- K5b: zero blocks of UT where d-block > e-block ----------------
__global__ void zero_upper() {
    int c = blockIdx.x, ib = blockIdx.y + 1;  // 1..7
    int tid = threadIdx.x;
    int r0 = tid >> 5;       // 0..7
    int c4 = tid & 31;
    int n4 = ib * 16;        // float4 columns to zero (cols 0..ib*64)
    float4 z = make_float4(0.f, 0.f, 0.f, 0.f);
    for (int rr = r0; rr < 64; rr += 8) {
        float4* row = (float4*)(g_UT + (size_t)c*DDm + (size_t)(ib*64 + rr)*Dm);
        for (int j4 = c4; j4 < n4; j4 += 32) row[j4] = z;
    }
}

// ---------------- K6: w_k = U_k mu_k ----------------
__global__ void compute_w(const float* __restrict__ muK) {
    int c = blockIdx.x;
    __shared__ float mus[Dm];
    int tid = threadIdx.x;
    for (int i = tid; i < Dm; i += 256) mus[i] = muK[(size_t)c*Dm + i];
    __syncthreads();
    const float* UT = g_UT + (size_t)c*DDm;
    for (int e = tid; e < Dm; e += 256) {
        float s = 0.f;
        for (int d = 0; d <= e; d++) s += UT[(size_t)d*Dm + e] * mus[d];
        g_w[(size_t)c*Dm + e] = s;
    }
}

// ---------------- K7: fused triangular GEMM + squared-distance + scores ----------------
// 128m x 128e block tile, BK=32, 8x8 thread tile, cp.async double buffering.
#define MAIN_SMEM (2*32*(128+128)*4)   // 64 KB

__device__ __forceinline__ void rda_load_tile(uint32_t sbase, int bufIdx,
        const float* xsrc, const float* usrc, int tid) {
    uint32_t xb = sbase + (uint32_t)bufIdx * 32768u;
    uint32_t ub = xb + 16384u;
    #pragma unroll
    for (int i = 0; i < 4; i++) {
        int lin = tid + i*256;
        int k = lin >> 5, v4 = (lin & 31) * 4;
        uint32_t xd = xb + (uint32_t)(k*128 + v4) * 4u;
        const float* xs = xsrc + (size_t)k*Nm + v4;
        asm volatile("cp.async.cg.shared.global [%0], [%1], 16;\n" :: "r"(xd), "l"(xs));
        uint32_t ud = ub + (uint32_t)(k*128 + v4) * 4u;
        const float* us = usrc + (size_t)k*Dm + v4;
        asm volatile("cp.async.cg.shared.global [%0], [%1], 16;\n" :: "r"(ud), "l"(us));
    }
    asm volatile("cp.async.commit_group;\n");
}

__global__ void __launch_bounds__(256, 2) rda_main(float* __restrict__ out) {
    int c  = blockIdx.y;
    int m0 = blockIdx.x * 128;
    extern __shared__ float sm[];
    uint32_t sbase = (uint32_t)__cvta_generic_to_shared(sm);
    const float* UT = g_UT + (size_t)c*DDm;
    int tid = threadIdx.x, tx = tid & 15, ty = tid >> 4;
    float q[8];
    #pragma unroll
    for (int a = 0; a < 8; a++) q[a] = 0.f;
    int buf = 0;

    for (int eb = 0; eb < 4; eb++) {
        int e0 = eb * 128;
        int nd = 4 * (eb + 1);
        float g[8][8];
        #pragma unroll
        for (int a = 0; a < 8; a++)
            #pragma unroll
            for (int b = 0; b < 8; b++) g[a][b] = 0.f;

        rda_load_tile(sbase, buf, g_XT + m0, UT + e0, tid);
        for (int t = 0; t < nd; t++) {
            asm volatile("cp.async.wait_group 0;\n" ::: "memory");
            __syncthreads();
            if (t + 1 < nd)
                rda_load_tile(sbase, buf ^ 1,
                              g_XT + (size_t)(t+1)*32*Nm + m0,
                              UT   + (size_t)(t+1)*32*Dm + e0, tid);
            const float* Xs = sm + buf*8192;
            const float* Us = Xs + 4096;
            #pragma unroll 8
            for (int k = 0; k < 32; k++) {
                float4 x0 = *(const float4*)&Xs[k*128 + ty*8];
                float4 x1 = *(const float4*)&Xs[k*128 + ty*8 + 4];
                float4 u0 = *(const float4*)&Us[k*128 + tx*8];
                float4 u1 = *(const float4*)&Us[k*128 + tx*8 + 4];
                float xa[8]  = {x0.x,x0.y,x0.z,x0.w,x1.x,x1.y,x1.z,x1.w};
                float ub8[8] = {u0.x,u0.y,u0.z,u0.w,u1.x,u1.y,u1.z,u1.w};
                #pragma unroll
                for (int a = 0; a < 8; a++)
                    #pragma unroll
                    for (int b = 0; b < 8; b++)
                        g[a][b] += xa[a] * ub8[b];
            }
            buf ^= 1;
        }
        __syncthreads();

        float4 w0 = *(const float4*)&g_w[(size_t)c*Dm + e0 + tx*8];
        float4 w1 = *(const float4*)&g_w[(size_t)c*Dm + e0 + tx*8 + 4];
        float wb[8] = {w0.x,w0.y,w0.z,w0.w,w1.x,w1.y,w1.z,w1.w};
        #pragma unroll
        for (int a = 0; a < 8; a++)
            #pragma unroll
            for (int b = 0; b < 8; b++) {
                float d = g[a][b] - wb[b];
                q[a] += d * d;
            }
    }

    #pragma unroll
    for (int off = 8; off > 0; off >>= 1)
        #pragma unroll
        for (int a = 0; a < 8; a++)
            q[a] += __shfl_xor_sync(0xffffffffu, q[a], off, 16);
    if (tx == 0) {
        float cc = g_cc[c];
        #pragma unroll
        for (int a = 0; a < 8; a++)
            out[(size_t)(m0 + ty*8 + a)*Cm + c] = cc - 0.5f*q[a];
    }
}

// ---------------- launcher ----------------
extern "C" void kernel_launch(void* const* d_in, const int* in_sizes, int n_in,
                              void* d_out, int out_size) {
    const float *X = nullptr, *muK = nullptr, *SigmaK = nullptr, *Sigma = nullptr, *cK = nullptr;
    for (int i = 0; i < n_in; i++) {
        switch (in_sizes[i]) {
            case Nm*Dm:        X      = (const float*)d_in[i]; break;
            case Cm*Dm:        muK    = (const float*)d_in[i]; break;
            case Cm*Dm*Dm:     SigmaK = (const float*)d_in[i]; break;
            case Dm*Dm:        Sigma  = (const float*)d_in[i]; break;
            case Cm:           cK     = (const float*)d_in[i]; break;
            default: break;
        }
    }
    if (!X || !muK || !SigmaK || !Sigma || !cK) return;

    cudaFuncSetAttribute(cholesky_k,    cudaFuncAttributeMaxDynamicSharedMemorySize, CHOL_SMEM);
    cudaFuncSetAttribute(trinv_offdiag, cudaFuncAttributeMaxDynamicSharedMemorySize, OFF_SMEM);
    cudaFuncSetAttribute(rda_main,      cudaFuncAttributeMaxDynamicSharedMemorySize, MAIN_SMEM);

    transpose_x<<<dim3(Nm/32, Dm/32), dim3(32, 8)>>>(X);
    build_M<<<Cm, 256>>>(SigmaK, Sigma);
    class_consts<<<1, 128>>>(cK);
    cholesky_k<<<Cm, 256, CHOL_SMEM>>>();
    diag_inv<<<Cm*8, 64>>>();
    trinv_offdiag<<<dim3(Cm, 7), 256, OFF_SMEM>>>();
    zero_upper<<<dim3(Cm, 7), 256>>>();
    compute_w<<<Cm, 256>>>(muK);
    rda_main<<<dim3(Nm/128, Cm), 256, MAIN_SMEM>>>((float*)d_out);
}

// round 3
// speedup vs baseline: 1.3538x; 1.0046x over previous
#include <cuda_runtime.h>
#include <math.h>
#include <stdint.h>

#define Dm 512
#define Cm 100
#define Nm 2048
#define DDm (Dm*Dm)

#define ALPHA 0.5f
#define SHRINK 1e-4f

typedef unsigned long long u64;

// ---------------- packed f32x2 helpers (sm_100+) ----------------
__device__ __forceinline__ u64 fdup(float v) {
    u64 r; asm("mov.b64 %0, {%1, %1};" : "=l"(r) : "f"(v)); return r;
}
__device__ __forceinline__ void f2unpack(u64 p, float& lo, float& hi) {
    asm("mov.b64 {%0, %1}, %2;" : "=f"(lo), "=f"(hi) : "l"(p));
}
__device__ __forceinline__ u64 ffma2(u64 a, u64 b, u64 c) {
    u64 d; asm("fma.rn.f32x2 %0, %1, %2, %3;" : "=l"(d) : "l"(a), "l"(b), "l"(c)); return d;
}
__device__ __forceinline__ u64 fadd2(u64 a, u64 b) {
    u64 d; asm("add.rn.f32x2 %0, %1, %2;" : "=l"(d) : "l"(a), "l"(b)); return d;
}

// ---------------- scratch (device globals; no runtime allocation) ----------------
__device__ float g_M[(size_t)Cm*DDm];    // M_k, overwritten in-place by L_k (lower)
__device__ float g_UT[(size_t)Cm*DDm];   // UT[d][e] = U[e][d],  U = L^{-1} (lower); upper zeroed
__device__ float g_XT[(size_t)Dm*Nm];    // X transposed [D][N]
__device__ float g_w[Cm*Dm];             // w_k = U_k mu_k
__device__ float g_cc[Cm];               // log(prior_k) - 0.25*log(fro2_k)  (or -inf)
__device__ float g_fro2[Cm];             // ||RegSigma_k||_F^2

// ---------------- K0: transpose X -> XT ----------------
__global__ void transpose_x(const float* __restrict__ X) {
    __shared__ float t[32][33];
    int bx = blockIdx.x * 32;   // n
    int by = blockIdx.y * 32;   // d
    int tx = threadIdx.x, ty0 = threadIdx.y;
    #pragma unroll
    for (int ty = ty0; ty < 32; ty += 8)
        t[ty][tx] = X[(size_t)(bx+ty)*Dm + by + tx];
    __syncthreads();
    #pragma unroll
    for (int ty = ty0; ty < 32; ty += 8)
        g_XT[(size_t)(by+ty)*Nm + bx + tx] = t[tx][ty];
}

// ---------------- K1: build M_k and Frobenius norm ----------------
__global__ void build_M(const float* __restrict__ SigmaK, const float* __restrict__ Sigma) {
    int c = blockIdx.x;
    const float4* Sk = (const float4*)(SigmaK + (size_t)c*DDm);
    const float4* Sg = (const float4*)Sigma;
    float4* M = (float4*)(g_M + (size_t)c*DDm);
    int tid = threadIdx.x;
    float fro = 0.f;
    for (int i = tid; i < DDm/4; i += 256) {
        float4 a = Sk[i];
        float4 b = Sg[i];
        int e0 = i*4;
        float r0 = ALPHA*a.x + (1.f-ALPHA)*b.x;
        float r1 = ALPHA*a.y + (1.f-ALPHA)*b.y;
        float r2 = ALPHA*a.z + (1.f-ALPHA)*b.z;
        float r3 = ALPHA*a.w + (1.f-ALPHA)*b.w;
        fro += r0*r0 + r1*r1 + r2*r2 + r3*r3;
        float4 m;
        m.x = (1.f-SHRINK)*r0 + ((((e0+0)>>9) == ((e0+0)&511)) ? SHRINK : 0.f);
        m.y = (1.f-SHRINK)*r1 + ((((e0+1)>>9) == ((e0+1)&511)) ? SHRINK : 0.f);
        m.z = (1.f-SHRINK)*r2 + ((((e0+2)>>9) == ((e0+2)&511)) ? SHRINK : 0.f);
        m.w = (1.f-SHRINK)*r3 + ((((e0+3)>>9) == ((e0+3)&511)) ? SHRINK : 0.f);
        M[i] = m;
    }
    __shared__ float red[256];
    red[tid] = fro;
    __syncthreads();
    for (int s = 128; s > 0; s >>= 1) {
        if (tid < s) red[tid] += red[tid+s];
        __syncthreads();
    }
    if (tid == 0) g_fro2[c] = red[0];
}

// ---------------- K2: per-class constants ----------------
__global__ void class_consts(const float* __restrict__ cK) {
    __shared__ float ssum[128];
    int tid = threadIdx.x;
    float s = 0.f;
    for (int i = tid; i < Cm; i += 128) s += cK[i];
    ssum[tid] = s;
    __syncthreads();
    for (int st = 64; st > 0; st >>= 1) {
        if (tid < st) ssum[tid] += ssum[tid+st];
        __syncthreads();
    }
    float tot = ssum[0];
    if (tid < Cm) {
        float ck = cK[tid];
        float cc;
        if (ck <= 0.f) cc = -INFINITY;
        else cc = logf(ck / tot) - 0.25f*logf(g_fro2[tid]);
        g_cc[tid] = cc;
    }
}

// ---------------- K3: left-looking blocked Cholesky (in place, lower) ----------------
#define CHOL_SMEM ((512*65 + 2*64*65)*4)
__global__ void __launch_bounds__(256) cholesky_k() {
    int c = blockIdx.x;
    float* A = g_M + (size_t)c*DDm;
    extern __shared__ float sm[];
    float* P  = sm;              // [512][65] panel
    float* Lt = sm + 512*65;     // [64][65] history block at panel-top rows
    float* Lr = Lt + 64*65;      // [64][65] history block at target rows
    float* colb = Lt;            // reuse Lt as scaled-column buffer during factorization
    int tid = threadIdx.x;
    int tx = tid & 15, ty = tid >> 4;
    for (int jb = 0; jb < 8; jb++) {
        int col0 = jb*64;
        int nr = Dm - col0;
        for (int i = tid; i < nr*64; i += 256) {
            int r = i >> 6, j = i & 63;
            P[r*65+j] = A[(size_t)(col0+r)*Dm + col0 + j];
        }
        __syncthreads();
        for (int kb = 0; kb < jb; kb++) {
            for (int i = tid; i < 64*64; i += 256) {
                int r = i >> 6, k = i & 63;
                Lt[r*65+k] = A[(size_t)(col0+r)*Dm + kb*64 + k];
            }
            __syncthreads();
            for (int r0 = 0; r0 < nr; r0 += 64) {
                const float* Lp = Lt;
                if (r0 != 0) {
                    for (int i = tid; i < 64*64; i += 256) {
                        int r = i >> 6, k = i & 63;
                        Lr[r*65+k] = A[(size_t)(col0+r0+r)*Dm + kb*64 + k];
                    }
                    Lp = Lr;
                }
                __syncthreads();
                float acc[4][4];
                #pragma unroll
                for (int a = 0; a < 4; a++)
                    #pragma unroll
                    for (int b = 0; b < 4; b++) acc[a][b] = 0.f;
                #pragma unroll 8
                for (int k = 0; k < 64; k++) {
                    float av[4], bv[4];
                    #pragma unroll
                    for (int a = 0; a < 4; a++) av[a] = Lp[(ty*4+a)*65 + k];
                    #pragma unroll
                    for (int b = 0; b < 4; b++) bv[b] = Lt[(tx*4+b)*65 + k];
                    #pragma unroll
                    for (int a = 0; a < 4; a++)
                        #pragma unroll
                        for (int b = 0; b < 4; b++) acc[a][b] += av[a]*bv[b];
                }
                #pragma unroll
                for (int a = 0; a < 4; a++)
                    #pragma unroll
                    for (int b = 0; b < 4; b++)
                        P[(r0+ty*4+a)*65 + tx*4+b] -= acc[a][b];
                __syncthreads();
            }
        }
        // factor 64-wide panel: 2 barriers per column, no single-thread serialization
        for (int j = 0; j < 64; j++) {
            __syncthreads();
            float s = rsqrtf(P[j*65+j]);
            for (int r = j+tid; r < nr; r += 256) colb[r] = P[r*65+j] * s;
            __syncthreads();
            for (int r = j+1+tid; r < nr; r += 256) {
                float lrj = colb[r];
                P[r*65+j] = lrj;
                #pragma unroll 4
                for (int k = j+1; k < 64; k++)
                    P[r*65+k] -= lrj * colb[k];
            }
            if (tid == 0) P[j*65+j] = colb[j];
        }
        __syncthreads();
        for (int i = tid; i < nr*64; i += 256) {
            int r = i >> 6, j = i & 63;
            A[(size_t)(col0+r)*Dm + col0 + j] = P[r*65+j];
        }
        __syncthreads();
    }
}

// ---------------- K4: invert 64x64 diagonal blocks of L, write into UT ----------------
__global__ void diag_inv() {
    int blk = blockIdx.x;
    int c = blk >> 3, ib = blk & 7;
    const float* A = g_M + (size_t)c*DDm + (size_t)(ib*64)*Dm + ib*64;
    float* UT = g_UT + (size_t)c*DDm;
    __shared__ float Ls[64][65];
    __shared__ float Xs[64][64];
    int t = threadIdx.x;  // column of inverse
    for (int r = 0; r < 64; r++) Ls[r][t] = A[(size_t)r*Dm + t];
    __syncthreads();
    for (int r = 0; r < 64; r++) {
        float v;
        if (r < t) v = 0.f;
        else if (r == t) v = 1.0f / Ls[r][r];
        else {
            float s = 0.f;
            for (int k = t; k < r; k++) s += Ls[r][k]*Xs[k][t];
            v = -s / Ls[r][r];
        }
        Xs[r][t] = v;
    }
    __syncthreads();
    for (int r = 0; r < 64; r++)
        UT[(size_t)(ib*64 + t)*Dm + ib*64 + r] = Xs[r][t];
}

// ---------------- K5: off-diagonal blocks of U = L^{-1}, parallel over columns j ----------------
#define OFF_SMEM (4*64*65*4)
__global__ void __launch_bounds__(256) trinv_offdiag() {
    int c = blockIdx.x;
    int j = blockIdx.y;            // 0..6
    const float* L = g_M + (size_t)c*DDm;
    float* UT = g_UT + (size_t)c*DDm;
    extern __shared__ float sm[];
    float* As  = sm;             // L_ik [r][kk]
    float* Bs  = As + 64*65;     // U_kj [kk][cj]
    float* Ts  = Bs + 64*65;     // T    [r][cj]
    float* Ais = Ts + 64*65;     // U_ii [r][kk]
    int tid = threadIdx.x, tx = tid & 15, ty = tid >> 4;
    for (int i = j+1; i < 8; i++) {
        float acc[4][4];
        #pragma unroll
        for (int a = 0; a < 4; a++)
            #pragma unroll
            for (int b = 0; b < 4; b++) acc[a][b] = 0.f;
        for (int kblk = j; kblk < i; kblk++) {
            __syncthreads();
            for (int idx = tid; idx < 64*64; idx += 256) {
                int r = idx >> 6, kk = idx & 63;
                As[r*65+kk] = L[(size_t)(i*64+r)*Dm + kblk*64 + kk];
            }
            for (int idx = tid; idx < 64*64; idx += 256) {
                int cj = idx >> 6, kk = idx & 63;
                Bs[kk*65+cj] = UT[(size_t)(j*64+cj)*Dm + kblk*64 + kk];
            }
            __syncthreads();
            #pragma unroll 8
            for (int kk = 0; kk < 64; kk++) {
                float av[4], bv[4];
                #pragma unroll
                for (int a = 0; a < 4; a++) av[a] = As[(ty*4+a)*65 + kk];
                #pragma unroll
                for (int b = 0; b < 4; b++) bv[b] = Bs[kk*65 + tx*4+b];
                #pragma unroll
                for (int a = 0; a < 4; a++)
                    #pragma unroll
                    for (int b = 0; b < 4; b++) acc[a][b] += av[a]*bv[b];
            }
        }
        __syncthreads();
        #pragma unroll
        for (int a = 0; a < 4; a++)
            #pragma unroll
            for (int b = 0; b < 4; b++)
                Ts[(ty*4+a)*65 + tx*4+b] = acc[a][b];
        for (int idx = tid; idx < 64*64; idx += 256) {
            int kk = idx >> 6, r = idx & 63;
            Ais[r*65+kk] = UT[(size_t)(i*64+kk)*Dm + i*64 + r];
        }
        __syncthreads();
        float acc2[4][4];
        #pragma unroll
        for (int a = 0; a < 4; a++)
            #pragma unroll
            for (int b = 0; b < 4; b++) acc2[a][b] = 0.f;
        #pragma unroll 8
        for (int kk = 0; kk < 64; kk++) {
            float av[4], bv[4];
            #pragma unroll
            for (int a = 0; a < 4; a++) av[a] = Ais[(ty*4+a)*65 + kk];
            #pragma unroll
            for (int b = 0; b < 4; b++) bv[b] = Ts[kk*65 + tx*4+b];
            #pragma unroll
            for (int a = 0; a < 4; a++)
                #pragma unroll
                for (int b = 0; b < 4; b++) acc2[a][b] += av[a]*bv[b];
        }
        #pragma unroll
        for (int b = 0; b < 4; b++)
            #pragma unroll
            for (int a = 0; a < 4; a++)
                UT[(size_t)(j*64 + tx*4+b)*Dm + i*64 + ty*4+a] = -acc2[a][b];
        __syncthreads();
    }
}

// ---------------- K5b: zero blocks of UT where d-block > e-block ----------------
__global__ void zero_upper() {
    int c = blockIdx.x, ib = blockIdx.y + 1;  // 1..7
    int tid = threadIdx.x;
    int r0 = tid >> 5;       // 0..7
    int c4 = tid & 31;
    int n4 = ib * 16;        // float4 columns to zero (cols 0..ib*64)
    float4 z = make_float4(0.f, 0.f, 0.f, 0.f);
    for (int rr = r0; rr < 64; rr += 8) {
        float4* row = (float4*)(g_UT + (size_t)c*DDm + (size_t)(ib*64 + rr)*Dm);
        for (int j4 = c4; j4 < n4; j4 += 32) row[j4] = z;
    }
}

// ---------------- K6: w_k = U_k mu_k ----------------
__global__ void compute_w(const float* __restrict__ muK) {
    int c = blockIdx.x;
    __shared__ float mus[Dm];
    int tid = threadIdx.x;
    for (int i = tid; i < Dm; i += 256) mus[i] = muK[(size_t)c*Dm + i];
    __syncthreads();
    const float* UT = g_UT + (size_t)c*DDm;
    for (int e = tid; e < Dm; e += 256) {
        float s = 0.f;
        for (int d = 0; d <= e; d++) s += UT[(size_t)d*Dm + e] * mus[d];
        g_w[(size_t)c*Dm + e] = s;
    }
}

// ---------------- K7: fused triangular GEMM + squared-distance + scores ----------------
// 128m x 128e block tile, BK=32, 8x8 thread tile via packed f32x2 FFMA,
// cp.async double buffering. m-dimension packed (pairs free from 128-bit loads),
// e-operand broadcast-duplicated.
#define MAIN_SMEM (2*32*(128+128)*4)   // 64 KB

__device__ __forceinline__ void rda_load_tile(uint32_t sbase, int bufIdx,
        const float* xsrc, const float* usrc, int tid) {
    uint32_t xb = sbase + (uint32_t)bufIdx * 32768u;
    uint32_t ub = xb + 16384u;
    #pragma unroll
    for (int i = 0; i < 4; i++) {
        int lin = tid + i*256;
        int k = lin >> 5, v4 = (lin & 31) * 4;
        uint32_t xd = xb + (uint32_t)(k*128 + v4) * 4u;
        const float* xs = xsrc + (size_t)k*Nm + v4;
        asm volatile("cp.async.cg.shared.global [%0], [%1], 16;\n" :: "r"(xd), "l"(xs));
        uint32_t ud = ub + (uint32_t)(k*128 + v4) * 4u;
        const float* us = usrc + (size_t)k*Dm + v4;
        asm volatile("cp.async.cg.shared.global [%0], [%1], 16;\n" :: "r"(ud), "l"(us));
    }
    asm volatile("cp.async.commit_group;\n");
}

__global__ void __launch_bounds__(256, 2) rda_main(float* __restrict__ out) {
    int c  = blockIdx.y;
    int m0 = blockIdx.x * 128;
    extern __shared__ float sm[];
    uint32_t sbase = (uint32_t)__cvta_generic_to_shared(sm);
    const float* UT = g_UT + (size_t)c*DDm;
    int tid = threadIdx.x, tx = tid & 15, ty = tid >> 4;
    u64 q2[4];
    #pragma unroll
    for (int a = 0; a < 4; a++) q2[a] = 0ull;
    int buf = 0;

    for (int eb = 0; eb < 4; eb++) {
        int e0 = eb * 128;
        int nd = 4 * (eb + 1);
        u64 g2[4][8];
        #pragma unroll
        for (int a = 0; a < 4; a++)
            #pragma unroll
            for (int b = 0; b < 8; b++) g2[a][b] = 0ull;

        rda_load_tile(sbase, buf, g_XT + m0, UT + e0, tid);
        for (int t = 0; t < nd; t++) {
            asm volatile("cp.async.wait_group 0;\n" ::: "memory");
            __syncthreads();
            if (t + 1 < nd)
                rda_load_tile(sbase, buf ^ 1,
                              g_XT + (size_t)(t+1)*32*Nm + m0,
                              UT   + (size_t)(t+1)*32*Dm + e0, tid);
            const float* Xs = sm + buf*8192;
            const float* Us = Xs + 4096;
            #pragma unroll 4
            for (int k = 0; k < 32; k++) {
                ulonglong2 xv0 = *(const ulonglong2*)&Xs[k*128 + ty*8];
                ulonglong2 xv1 = *(const ulonglong2*)&Xs[k*128 + ty*8 + 4];
                u64 xa[4] = {xv0.x, xv0.y, xv1.x, xv1.y};
                float4 u0 = *(const float4*)&Us[k*128 + tx*8];
                float4 u1 = *(const float4*)&Us[k*128 + tx*8 + 4];
                u64 ud8[8] = {fdup(u0.x), fdup(u0.y), fdup(u0.z), fdup(u0.w),
                              fdup(u1.x), fdup(u1.y), fdup(u1.z), fdup(u1.w)};
                #pragma unroll
                for (int a = 0; a < 4; a++)
                    #pragma unroll
                    for (int b = 0; b < 8; b++)
                        g2[a][b] = ffma2(xa[a], ud8[b], g2[a][b]);
            }
            buf ^= 1;
        }
        __syncthreads();

        float4 w0 = *(const float4*)&g_w[(size_t)c*Dm + e0 + tx*8];
        float4 w1 = *(const float4*)&g_w[(size_t)c*Dm + e0 + tx*8 + 4];
        u64 wn[8] = {fdup(-w0.x), fdup(-w0.y), fdup(-w0.z), fdup(-w0.w),
                     fdup(-w1.x), fdup(-w1.y), fdup(-w1.z), fdup(-w1.w)};
        #pragma unroll
        for (int a = 0; a < 4; a++)
            #pragma unroll
            for (int b = 0; b < 8; b++) {
                u64 d = fadd2(g2[a][b], wn[b]);
                q2[a] = ffma2(d, d, q2[a]);
            }
    }

    float q[8];
    #pragma unroll
    for (int a = 0; a < 4; a++) f2unpack(q2[a], q[2*a], q[2*a+1]);
    #pragma unroll
    for (int off = 8; off > 0; off >>= 1)
        #pragma unroll
        for (int a = 0; a < 8; a++)
            q[a] += __shfl_xor_sync(0xffffffffu, q[a], off, 16);
    if (tx == 0) {
        float cc = g_cc[c];
        #pragma unroll
        for (int a = 0; a < 8; a++)
            out[(size_t)(m0 + ty*8 + a)*Cm + c] = cc - 0.5f*q[a];
    }
}

// ---------------- launcher ----------------
extern "C" void kernel_launch(void* const* d_in, const int* in_sizes, int n_in,
                              void* d_out, int out_size) {
    const float *X = nullptr, *muK = nullptr, *SigmaK = nullptr, *Sigma = nullptr, *cK = nullptr;
    for (int i = 0; i < n_in; i++) {
        switch (in_sizes[i]) {
            case Nm*Dm:        X      = (const float*)d_in[i]; break;
            case Cm*Dm:        muK    = (const float*)d_in[i]; break;
            case Cm*Dm*Dm:     SigmaK = (const float*)d_in[i]; break;
            case Dm*Dm:        Sigma  = (const float*)d_in[i]; break;
            case Cm:           cK     = (const float*)d_in[i]; break;
            default: break;
        }
    }
    if (!X || !muK || !SigmaK || !Sigma || !cK) return;

    cudaFuncSetAttribute(cholesky_k,    cudaFuncAttributeMaxDynamicSharedMemorySize, CHOL_SMEM);
    cudaFuncSetAttribute(trinv_offdiag, cudaFuncAttributeMaxDynamicSharedMemorySize, OFF_SMEM);
    cudaFuncSetAttribute(rda_main,      cudaFuncAttributeMaxDynamicSharedMemorySize, MAIN_SMEM);

    transpose_x<<<dim3(Nm/32, Dm/32), dim3(32, 8)>>>(X);
    build_M<<<Cm, 256>>>(SigmaK, Sigma);
    class_consts<<<1, 128>>>(cK);
    cholesky_k<<<Cm, 256, CHOL_SMEM>>>();
    diag_inv<<<Cm*8, 64>>>();
    trinv_offdiag<<<dim3(Cm, 7), 256, OFF_SMEM>>>();
    zero_upper<<<dim3(Cm, 7), 256>>>();
    compute_w<<<Cm, 256>>>(muK);
    rda_main<<<dim3(Nm/128, Cm), 256, MAIN_SMEM>>>((float*)d_out);
}

// round 4
// speedup vs baseline: 1.5481x; 1.1435x over previous
#include <cuda_runtime.h>
#include <math.h>
#include <stdint.h>

#define Dm 512
#define Cm 100
#define Nm 2048
#define DDm (Dm*Dm)

#define ALPHA 0.5f
#define SHRINK 1e-4f

typedef unsigned long long u64;

// ---------------- packed f32x2 helpers (sm_100+) ----------------
__device__ __forceinline__ u64 fdup(float v) {
    u64 r; asm("mov.b64 %0, {%1, %1};" : "=l"(r) : "f"(v)); return r;
}
__device__ __forceinline__ void f2unpack(u64 p, float& lo, float& hi) {
    asm("mov.b64 {%0, %1}, %2;" : "=f"(lo), "=f"(hi) : "l"(p));
}
__device__ __forceinline__ u64 ffma2(u64 a, u64 b, u64 c) {
    u64 d; asm("fma.rn.f32x2 %0, %1, %2, %3;" : "=l"(d) : "l"(a), "l"(b), "l"(c)); return d;
}
__device__ __forceinline__ u64 fadd2(u64 a, u64 b) {
    u64 d; asm("add.rn.f32x2 %0, %1, %2;" : "=l"(d) : "l"(a), "l"(b)); return d;
}

// ---------------- scratch (device globals; no runtime allocation) ----------------
__device__ float g_M[(size_t)Cm*DDm];    // M_k, overwritten in-place by L_k (lower)
__device__ float g_UT[(size_t)Cm*DDm];   // UT[d][e] = U[e][d],  U = L^{-1} (lower); upper zeroed
__device__ float g_XT[(size_t)Dm*Nm];    // X transposed [D][N]
__device__ float g_w[Cm*Dm];             // w_k = U_k mu_k
__device__ float g_cc[Cm];               // log(prior_k) - 0.25*log(fro2_k)  (or -inf)
__device__ float g_fro2[Cm];             // ||RegSigma_k||_F^2

// ---------------- K0: transpose X -> XT ----------------
__global__ void transpose_x(const float* __restrict__ X) {
    __shared__ float t[32][33];
    int bx = blockIdx.x * 32;   // n
    int by = blockIdx.y * 32;   // d
    int tx = threadIdx.x, ty0 = threadIdx.y;
    #pragma unroll
    for (int ty = ty0; ty < 32; ty += 8)
        t[ty][tx] = X[(size_t)(bx+ty)*Dm + by + tx];
    __syncthreads();
    #pragma unroll
    for (int ty = ty0; ty < 32; ty += 8)
        g_XT[(size_t)(by+ty)*Nm + bx + tx] = t[tx][ty];
}

// ---------------- K1: build M_k and Frobenius norm ----------------
__global__ void build_M(const float* __restrict__ SigmaK, const float* __restrict__ Sigma) {
    int c = blockIdx.x;
    const float4* Sk = (const float4*)(SigmaK + (size_t)c*DDm);
    const float4* Sg = (const float4*)Sigma;
    float4* M = (float4*)(g_M + (size_t)c*DDm);
    int tid = threadIdx.x;
    float fro = 0.f;
    for (int i = tid; i < DDm/4; i += 256) {
        float4 a = Sk[i];
        float4 b = Sg[i];
        int e0 = i*4;
        float r0 = ALPHA*a.x + (1.f-ALPHA)*b.x;
        float r1 = ALPHA*a.y + (1.f-ALPHA)*b.y;
        float r2 = ALPHA*a.z + (1.f-ALPHA)*b.z;
        float r3 = ALPHA*a.w + (1.f-ALPHA)*b.w;
        fro += r0*r0 + r1*r1 + r2*r2 + r3*r3;
        float4 m;
        m.x = (1.f-SHRINK)*r0 + ((((e0+0)>>9) == ((e0+0)&511)) ? SHRINK : 0.f);
        m.y = (1.f-SHRINK)*r1 + ((((e0+1)>>9) == ((e0+1)&511)) ? SHRINK : 0.f);
        m.z = (1.f-SHRINK)*r2 + ((((e0+2)>>9) == ((e0+2)&511)) ? SHRINK : 0.f);
        m.w = (1.f-SHRINK)*r3 + ((((e0+3)>>9) == ((e0+3)&511)) ? SHRINK : 0.f);
        M[i] = m;
    }
    __shared__ float red[256];
    red[tid] = fro;
    __syncthreads();
    for (int s = 128; s > 0; s >>= 1) {
        if (tid < s) red[tid] += red[tid+s];
        __syncthreads();
    }
    if (tid == 0) g_fro2[c] = red[0];
}

// ---------------- K2: per-class constants ----------------
__global__ void class_consts(const float* __restrict__ cK) {
    __shared__ float ssum[128];
    int tid = threadIdx.x;
    float s = 0.f;
    for (int i = tid; i < Cm; i += 128) s += cK[i];
    ssum[tid] = s;
    __syncthreads();
    for (int st = 64; st > 0; st >>= 1) {
        if (tid < st) ssum[tid] += ssum[tid+st];
        __syncthreads();
    }
    float tot = ssum[0];
    if (tid < Cm) {
        float ck = cK[tid];
        float cc;
        if (ck <= 0.f) cc = -INFINITY;
        else cc = logf(ck / tot) - 0.25f*logf(g_fro2[tid]);
        g_cc[tid] = cc;
    }
}

// ---------------- K3a: right-looking panel factorization ----------------
// Factors the 64-wide panel at column jb*64 (rows jb*64..511) in smem.
#define PST 68
#define PANEL_SMEM ((512*PST + 512)*4)
__global__ void __launch_bounds__(256) chol_panel(int jb) {
    int c = blockIdx.x;
    int col0 = jb*64;
    int nr = Dm - col0;
    float* A = g_M + (size_t)c*DDm;
    extern __shared__ float sm[];
    float* P = sm;                 // [nr][PST]
    float* colb = sm + 512*PST;    // [nr] current scaled column
    int tid = threadIdx.x;

    // load panel (rows col0.., cols col0..col0+64)
    for (int i = tid; i < nr*16; i += 256) {
        int r = i >> 4, c4 = (i & 15) * 4;
        *(float4*)&P[r*PST + c4] = *(const float4*)&A[(size_t)(col0+r)*Dm + col0 + c4];
    }
    __syncthreads();

    for (int j = 0; j < 64; j++) {
        float s = rsqrtf(P[j*PST + j]);
        for (int r = j + tid; r < nr; r += 256) {
            float v = P[r*PST + j] * s;
            P[r*PST + j] = v;
            colb[r] = v;
        }
        __syncthreads();
        int k0 = j + 1;
        int k0a = (k0 + 3) & ~3;
        if (k0a > 64) k0a = 64;
        for (int r = j+1+tid; r < nr; r += 256) {
            float rj = colb[r];
            float* Pr = &P[r*PST];
            for (int k = k0; k < k0a; k++) Pr[k] -= rj * colb[k];
            for (int k = k0a; k < 64; k += 4) {
                float4 p = *(float4*)&Pr[k];
                float4 cb = *(const float4*)&colb[k];
                p.x -= rj*cb.x; p.y -= rj*cb.y; p.z -= rj*cb.z; p.w -= rj*cb.w;
                *(float4*)&Pr[k] = p;
            }
        }
        __syncthreads();
    }

    for (int i = tid; i < nr*16; i += 256) {
        int r = i >> 4, c4 = (i & 15) * 4;
        *(float4*)&A[(size_t)(col0+r)*Dm + col0 + c4] = *(const float4*)&P[r*PST + c4];
    }
}

// ---------------- K3b: trailing update, one 64x64 tile per block ----------------
// C_ij -= L_i * L_j^T for tile pair (i,j), i >= j > jb, k-depth 64 at column jb*64.
__global__ void __launch_bounds__(128) chol_update(int jb) {
    int c = blockIdx.x;
    int T = 7 - jb;                // trailing tile-rows
    // linear idx -> (a>=b) pair in T x T lower triangle
    int idx = blockIdx.y;
    int b = 0;
    while (idx >= T - b) { idx -= T - b; b++; }
    int a = b + idx;
    int i = jb + 1 + a;
    int j = jb + 1 + b;
    int col0 = jb*64;
    float* A = g_M + (size_t)c*DDm;

    __shared__ float As[64*65];
    __shared__ float Bs[64*65];
    int tid = threadIdx.x;
    int tx = tid & 15, ty = tid >> 4;   // tx: 16 col-groups of 4, ty: 8 row-groups of 8

    // stage L_i and L_j tiles (k-major rows)
    for (int t = tid; t < 1024; t += 128) {
        int r = t >> 4, c4 = (t & 15) * 4;
        float4 v = *(const float4*)&A[(size_t)(i*64 + r)*Dm + col0 + c4];
        As[r*65 + c4+0] = v.x; As[r*65 + c4+1] = v.y;
        As[r*65 + c4+2] = v.z; As[r*65 + c4+3] = v.w;
        float4 w = *(const float4*)&A[(size_t)(j*64 + r)*Dm + col0 + c4];
        Bs[r*65 + c4+0] = w.x; Bs[r*65 + c4+1] = w.y;
        Bs[r*65 + c4+2] = w.z; Bs[r*65 + c4+3] = w.w;
    }
    __syncthreads();

    float acc[8][4];
    #pragma unroll
    for (int p = 0; p < 8; p++)
        #pragma unroll
        for (int q = 0; q < 4; q++) acc[p][q] = 0.f;
    #pragma unroll 8
    for (int k = 0; k < 64; k++) {
        float av[8], bv[4];
        #pragma unroll
        for (int p = 0; p < 8; p++) av[p] = As[(ty*8+p)*65 + k];
        #pragma unroll
        for (int q = 0; q < 4; q++) bv[q] = Bs[(tx*4+q)*65 + k];
        #pragma unroll
        for (int p = 0; p < 8; p++)
            #pragma unroll
            for (int q = 0; q < 4; q++) acc[p][q] += av[p]*bv[q];
    }

    // C_ij RMW
    #pragma unroll
    for (int p = 0; p < 8; p++) {
        size_t off = (size_t)(i*64 + ty*8 + p)*Dm + j*64 + tx*4;
        float4 v = *(const float4*)&A[off];
        v.x -= acc[p][0]; v.y -= acc[p][1]; v.z -= acc[p][2]; v.w -= acc[p][3];
        *(float4*)&A[off] = v;
    }
}

// ---------------- K4: invert 64x64 diagonal blocks of L, write into UT ----------------
__global__ void diag_inv() {
    int blk = blockIdx.x;
    int c = blk >> 3, ib = blk & 7;
    const float* A = g_M + (size_t)c*DDm + (size_t)(ib*64)*Dm + ib*64;
    float* UT = g_UT + (size_t)c*DDm;
    __shared__ float Ls[64][65];
    __shared__ float Xs[64][64];
    int t = threadIdx.x;  // column of inverse
    for (int r = 0; r < 64; r++) Ls[r][t] = A[(size_t)r*Dm + t];
    __syncthreads();
    for (int r = 0; r < 64; r++) {
        float v;
        if (r < t) v = 0.f;
        else if (r == t) v = 1.0f / Ls[r][r];
        else {
            float s = 0.f;
            for (int k = t; k < r; k++) s += Ls[r][k]*Xs[k][t];
            v = -s / Ls[r][r];
        }
        Xs[r][t] = v;
    }
    __syncthreads();
    for (int r = 0; r < 64; r++)
        UT[(size_t)(ib*64 + t)*Dm + ib*64 + r] = Xs[r][t];
}

// ---------------- K5: off-diagonal blocks of U = L^{-1}, parallel over columns j ----------------
#define OFF_SMEM (4*64*65*4)
__global__ void __launch_bounds__(256) trinv_offdiag() {
    int c = blockIdx.x;
    int j = blockIdx.y;            // 0..6
    const float* L = g_M + (size_t)c*DDm;
    float* UT = g_UT + (size_t)c*DDm;
    extern __shared__ float sm[];
    float* As  = sm;             // L_ik [r][kk]
    float* Bs  = As + 64*65;     // U_kj [kk][cj]
    float* Ts  = Bs + 64*65;     // T    [r][cj]
    float* Ais = Ts + 64*65;     // U_ii [r][kk]
    int tid = threadIdx.x, tx = tid & 15, ty = tid >> 4;
    for (int i = j+1; i < 8; i++) {
        float acc[4][4];
        #pragma unroll
        for (int a = 0; a < 4; a++)
            #pragma unroll
            for (int b = 0; b < 4; b++) acc[a][b] = 0.f;
        for (int kblk = j; kblk < i; kblk++) {
            __syncthreads();
            for (int idx = tid; idx < 64*64; idx += 256) {
                int r = idx >> 6, kk = idx & 63;
                As[r*65+kk] = L[(size_t)(i*64+r)*Dm + kblk*64 + kk];
            }
            for (int idx = tid; idx < 64*64; idx += 256) {
                int cj = idx >> 6, kk = idx & 63;
                Bs[kk*65+cj] = UT[(size_t)(j*64+cj)*Dm + kblk*64 + kk];
            }
            __syncthreads();
            #pragma unroll 8
            for (int kk = 0; kk < 64; kk++) {
                float av[4], bv[4];
                #pragma unroll
                for (int a = 0; a < 4; a++) av[a] = As[(ty*4+a)*65 + kk];
                #pragma unroll
                for (int b = 0; b < 4; b++) bv[b] = Bs[kk*65 + tx*4+b];
                #pragma unroll
                for (int a = 0; a < 4; a++)
                    #pragma unroll
                    for (int b = 0; b < 4; b++) acc[a][b] += av[a]*bv[b];
            }
        }
        __syncthreads();
        #pragma unroll
        for (int a = 0; a < 4; a++)
            #pragma unroll
            for (int b = 0; b < 4; b++)
                Ts[(ty*4+a)*65 + tx*4+b] = acc[a][b];
        for (int idx = tid; idx < 64*64; idx += 256) {
            int kk = idx >> 6, r = idx & 63;
            Ais[r*65+kk] = UT[(size_t)(i*64+kk)*Dm + i*64 + r];
        }
        __syncthreads();
        float acc2[4][4];
        #pragma unroll
        for (int a = 0; a < 4; a++)
            #pragma unroll
            for (int b = 0; b < 4; b++) acc2[a][b] = 0.f;
        #pragma unroll 8
        for (int kk = 0; kk < 64; kk++) {
            float av[4], bv[4];
            #pragma unroll
            for (int a = 0; a < 4; a++) av[a] = Ais[(ty*4+a)*65 + kk];
            #pragma unroll
            for (int b = 0; b < 4; b++) bv[b] = Ts[kk*65 + tx*4+b];
            #pragma unroll
            for (int a = 0; a < 4; a++)
                #pragma unroll
                for (int b = 0; b < 4; b++) acc2[a][b] += av[a]*bv[b];
        }
        #pragma unroll
        for (int b = 0; b < 4; b++)
            #pragma unroll
            for (int a = 0; a < 4; a++)
                UT[(size_t)(j*64 + tx*4+b)*Dm + i*64 + ty*4+a] = -acc2[a][b];
        __syncthreads();
    }
}

// ---------------- K5b: zero blocks of UT where d-block > e-block ----------------
__global__ void zero_upper() {
    int c = blockIdx.x, ib = blockIdx.y + 1;  // 1..7
    int tid = threadIdx.x;
    int r0 = tid >> 5;       // 0..7
    int c4 = tid & 31;
    int n4 = ib * 16;        // float4 columns to zero (cols 0..ib*64)
    float4 z = make_float4(0.f, 0.f, 0.f, 0.f);
    for (int rr = r0; rr < 64; rr += 8) {
        float4* row = (float4*)(g_UT + (size_t)c*DDm + (size_t)(ib*64 + rr)*Dm);
        for (int j4 = c4; j4 < n4; j4 += 32) row[j4] = z;
    }
}

// ---------------- K6: w_k = U_k mu_k ----------------
__global__ void compute_w(const float* __restrict__ muK) {
    int c = blockIdx.x;
    __shared__ float mus[Dm];
    int tid = threadIdx.x;
    for (int i = tid; i < Dm; i += 256) mus[i] = muK[(size_t)c*Dm + i];
    __syncthreads();
    const float* UT = g_UT + (size_t)c*DDm;
    for (int e = tid; e < Dm; e += 256) {
        float s = 0.f;
        for (int d = 0; d <= e; d++) s += UT[(size_t)d*Dm + e] * mus[d];
        g_w[(size_t)c*Dm + e] = s;
    }
}

// ---------------- K7: fused triangular GEMM + squared-distance + scores ----------------
// 128m x 128e block tile, BK=32, 8x8 thread tile via packed f32x2 FFMA,
// cp.async double buffering.
#define MAIN_SMEM (2*32*(128+128)*4)   // 64 KB

__device__ __forceinline__ void rda_load_tile(uint32_t sbase, int bufIdx,
        const float* xsrc, const float* usrc, int tid) {
    uint32_t xb = sbase + (uint32_t)bufIdx * 32768u;
    uint32_t ub = xb + 16384u;
    #pragma unroll
    for (int i = 0; i < 4; i++) {
        int lin = tid + i*256;
        int k = lin >> 5, v4 = (lin & 31) * 4;
        uint32_t xd = xb + (uint32_t)(k*128 + v4) * 4u;
        const float* xs = xsrc + (size_t)k*Nm + v4;
        asm volatile("cp.async.cg.shared.global [%0], [%1], 16;\n" :: "r"(xd), "l"(xs));
        uint32_t ud = ub + (uint32_t)(k*128 + v4) * 4u;
        const float* us = usrc + (size_t)k*Dm + v4;
        asm volatile("cp.async.cg.shared.global [%0], [%1], 16;\n" :: "r"(ud), "l"(us));
    }
    asm volatile("cp.async.commit_group;\n");
}

__global__ void __launch_bounds__(256, 2) rda_main(float* __restrict__ out) {
    int c  = blockIdx.y;
    int m0 = blockIdx.x * 128;
    extern __shared__ float sm[];
    uint32_t sbase = (uint32_t)__cvta_generic_to_shared(sm);
    const float* UT = g_UT + (size_t)c*DDm;
    int tid = threadIdx.x, tx = tid & 15, ty = tid >> 4;
    u64 q2[4];
    #pragma unroll
    for (int a = 0; a < 4; a++) q2[a] = 0ull;
    int buf = 0;

    for (int eb = 0; eb < 4; eb++) {
        int e0 = eb * 128;
        int nd = 4 * (eb + 1);
        u64 g2[4][8];
        #pragma unroll
        for (int a = 0; a < 4; a++)
            #pragma unroll
            for (int b = 0; b < 8; b++) g2[a][b] = 0ull;

        rda_load_tile(sbase, buf, g_XT + m0, UT + e0, tid);
        for (int t = 0; t < nd; t++) {
            asm volatile("cp.async.wait_group 0;\n" ::: "memory");
            __syncthreads();
            if (t + 1 < nd)
                rda_load_tile(sbase, buf ^ 1,
                              g_XT + (size_t)(t+1)*32*Nm + m0,
                              UT   + (size_t)(t+1)*32*Dm + e0, tid);
            const float* Xs = sm + buf*8192;
            const float* Us = Xs + 4096;
            #pragma unroll 4
            for (int k = 0; k < 32; k++) {
                ulonglong2 xv0 = *(const ulonglong2*)&Xs[k*128 + ty*8];
                ulonglong2 xv1 = *(const ulonglong2*)&Xs[k*128 + ty*8 + 4];
                u64 xa[4] = {xv0.x, xv0.y, xv1.x, xv1.y};
                float4 u0 = *(const float4*)&Us[k*128 + tx*8];
                float4 u1 = *(const float4*)&Us[k*128 + tx*8 + 4];
                u64 ud8[8] = {fdup(u0.x), fdup(u0.y), fdup(u0.z), fdup(u0.w),
                              fdup(u1.x), fdup(u1.y), fdup(u1.z), fdup(u1.w)};
                #pragma unroll
                for (int a = 0; a < 4; a++)
                    #pragma unroll
                    for (int b = 0; b < 8; b++)
                        g2[a][b] = ffma2(xa[a], ud8[b], g2[a][b]);
            }
            buf ^= 1;
        }
        __syncthreads();

        float4 w0 = *(const float4*)&g_w[(size_t)c*Dm + e0 + tx*8];
        float4 w1 = *(const float4*)&g_w[(size_t)c*Dm + e0 + tx*8 + 4];
        u64 wn[8] = {fdup(-w0.x), fdup(-w0.y), fdup(-w0.z), fdup(-w0.w),
                     fdup(-w1.x), fdup(-w1.y), fdup(-w1.z), fdup(-w1.w)};
        #pragma unroll
        for (int a = 0; a < 4; a++)
            #pragma unroll
            for (int b = 0; b < 8; b++) {
                u64 d = fadd2(g2[a][b], wn[b]);
                q2[a] = ffma2(d, d, q2[a]);
            }
    }

    float q[8];
    #pragma unroll
    for (int a = 0; a < 4; a++) f2unpack(q2[a], q[2*a], q[2*a+1]);
    #pragma unroll
    for (int off = 8; off > 0; off >>= 1)
        #pragma unroll
        for (int a = 0; a < 8; a++)
            q[a] += __shfl_xor_sync(0xffffffffu, q[a], off, 16);
    if (tx == 0) {
        float cc = g_cc[c];
        #pragma unroll
        for (int a = 0; a < 8; a++)
            out[(size_t)(m0 + ty*8 + a)*Cm + c] = cc - 0.5f*q[a];
    }
}

// ---------------- launcher ----------------
extern "C" void kernel_launch(void* const* d_in, const int* in_sizes, int n_in,
                              void* d_out, int out_size) {
    const float *X = nullptr, *muK = nullptr, *SigmaK = nullptr, *Sigma = nullptr, *cK = nullptr;
    for (int i = 0; i < n_in; i++) {
        switch (in_sizes[i]) {
            case Nm*Dm:        X      = (const float*)d_in[i]; break;
            case Cm*Dm:        muK    = (const float*)d_in[i]; break;
            case Cm*Dm*Dm:     SigmaK = (const float*)d_in[i]; break;
            case Dm*Dm:        Sigma  = (const float*)d_in[i]; break;
            case Cm:           cK     = (const float*)d_in[i]; break;
            default: break;
        }
    }
    if (!X || !muK || !SigmaK || !Sigma || !cK) return;

    cudaFuncSetAttribute(chol_panel,    cudaFuncAttributeMaxDynamicSharedMemorySize, PANEL_SMEM);
    cudaFuncSetAttribute(trinv_offdiag, cudaFuncAttributeMaxDynamicSharedMemorySize, OFF_SMEM);
    cudaFuncSetAttribute(rda_main,      cudaFuncAttributeMaxDynamicSharedMemorySize, MAIN_SMEM);

    transpose_x<<<dim3(Nm/32, Dm/32), dim3(32, 8)>>>(X);
    build_M<<<Cm, 256>>>(SigmaK, Sigma);
    class_consts<<<1, 128>>>(cK);

    for (int jb = 0; jb < 8; jb++) {
        chol_panel<<<Cm, 256, PANEL_SMEM>>>(jb);
        int T = 7 - jb;
        if (T > 0) {
            int nt = T * (T + 1) / 2;
            chol_update<<<dim3(Cm, nt), 128>>>(jb);
        }
    }

    diag_inv<<<Cm*8, 64>>>();
    trinv_offdiag<<<dim3(Cm, 7), 256, OFF_SMEM>>>();
    zero_upper<<<dim3(Cm, 7), 256>>>();
    compute_w<<<Cm, 256>>>(muK);
    rda_main<<<dim3(Nm/128, Cm), 256, MAIN_SMEM>>>((float*)d_out);
}